// round 15
// baseline (speedup 1.0000x reference)
#include <cuda_runtime.h>
#include <cuda_bf16.h>
#include <math.h>

// Shapes (fixed by the problem)
#define BATCH 16
#define CHAN  256
#define HH_   224
#define WW_   224
#define PLANE_ELEMS (HH_ * WW_)          // 50176 floats per plane
#define PLANE_V4    (PLANE_ELEMS / 4)    // 12544 float4 per plane
#define NPLANES     (BATCH * CHAN)       // 4096
#define W4_PER_ROW  (WW_ / 4)            // 56 float4 per row
#define SUB_ELEMS   (112 * 112)

#define NT 512                            // threads per CTA (one plane per CTA)

// Scratch globals — all counters MONOTONIC (never reset): no init kernel.
// Runs are stream-serialized so per-run phases are clean.
__device__ float    g_sums[NPLANES * 4];
__device__ float    g_scale[NPLANES];
__device__ unsigned g_done[BATCH];   // arrivals per batch (256 per run)
__device__ unsigned g_flag[BATCH];   // head publishes 256*(run+1)

// ---------------------------------------------------------------------------
// Fused kernel: CTA = one plane.
//   1) sum own plane (pulls it through L2; 444 resident CTAs x 200KB = 88MB,
//      fits in the 126MB L2)
//   2) per-batch arrival; last arriver computes the head, publishes flag
//   3) wait for own batch's flag (produce-before-wait: waiters depend only on
//      already-issued, resident CTAs -> no starvation, bounded spin)
//   4) re-read own plane (expected L2 hit), scale, evict-first store
// ---------------------------------------------------------------------------
__global__ __launch_bounds__(NT) void fused_kernel(
        const float* __restrict__ x, float* __restrict__ out,
        const float* __restrict__ w1, const float* __restrict__ w2,
        const float* __restrict__ w_enc) {
    const int plane = blockIdx.x;
    const int b = plane >> 8;
    const int t = threadIdx.x;
    const int lane = t & 31, wid = t >> 5;          // 16 warps

    const float4* __restrict__ p = (const float4*)x + (size_t)plane * PLANE_V4;

    // ---------------- Phase 1: parity sums (default cache policy: retain) --
    float a0 = 0.f, a1 = 0.f, a2 = 0.f, a3 = 0.f;
    #pragma unroll 5
    for (int i = t; i < PLANE_V4; i += NT) {
        float4 v = p[i];
        int h = i / W4_PER_ROW;
        float ev = v.x + v.z;
        float od = v.y + v.w;
        if (h & 1) { a1 += ev; a3 += od; }
        else       { a0 += ev; a2 += od; }
    }
    #pragma unroll
    for (int off = 16; off > 0; off >>= 1) {
        a0 += __shfl_down_sync(0xffffffffu, a0, off);
        a1 += __shfl_down_sync(0xffffffffu, a1, off);
        a2 += __shfl_down_sync(0xffffffffu, a2, off);
        a3 += __shfl_down_sync(0xffffffffu, a3, off);
    }

    __shared__ float red[16][4];
    __shared__ unsigned s_old;
    if (lane == 0) { red[wid][0] = a0; red[wid][1] = a1; red[wid][2] = a2; red[wid][3] = a3; }
    __syncthreads();
    if (t < 4) {
        float acc = 0.f;
        #pragma unroll
        for (int w = 0; w < 16; w++) acc += red[w][t];
        g_sums[(size_t)plane * 4 + t] = acc;
        __threadfence();
    }
    __syncthreads();
    if (t == 0) s_old = atomicAdd(&g_done[b], 1u);
    __syncthreads();
    const unsigned old = s_old;

    if ((old & 255u) == 255u) {
        // ---- last arriver of batch b this run: inline head ----
        __shared__ float ori[4][CHAN];
        __shared__ float ysh[CHAN];
        __shared__ float hsh[CHAN / 2];
        __shared__ float rr[8][4];
        __shared__ int s_top;

        const int c = t;                 // only c < 256 participates in math
        float LL = 0.f, HL = 0.f, LH = 0.f, HHb = 0.f;
        if (c < CHAN) {
            const float inv = 0.5f / (float)SUB_ELEMS;
            const size_t gi = ((size_t)b * CHAN + c) * 4;
            float m1 = __ldcg(&g_sums[gi + 0]) * inv;
            float m2 = __ldcg(&g_sums[gi + 1]) * inv;
            float m3 = __ldcg(&g_sums[gi + 2]) * inv;
            float m4 = __ldcg(&g_sums[gi + 3]) * inv;
            LL  =  m1 + m2 + m3 + m4;
            HL  = -m1 - m2 + m3 + m4;
            LH  = -m1 + m2 - m3 + m4;
            HHb =  m1 - m2 - m3 + m4;
            ori[0][c] = LL; ori[1][c] = HL; ori[2][c] = LH; ori[3][c] = HHb;

            float we = w_enc[c];
            float p0 = LL * we, p1 = HL * we, p2 = LH * we, p3 = HHb * we;
            #pragma unroll
            for (int off = 16; off > 0; off >>= 1) {
                p0 += __shfl_down_sync(0xffffffffu, p0, off);
                p1 += __shfl_down_sync(0xffffffffu, p1, off);
                p2 += __shfl_down_sync(0xffffffffu, p2, off);
                p3 += __shfl_down_sync(0xffffffffu, p3, off);
            }
            if (lane == 0) { rr[wid][0] = p0; rr[wid][1] = p1; rr[wid][2] = p2; rr[wid][3] = p3; }
        }
        __syncthreads();
        if (t == 0) {
            float l0 = 0.f, l1 = 0.f, l2 = 0.f, l3 = 0.f;
            #pragma unroll
            for (int w = 0; w < 8; w++) { l0 += rr[w][0]; l1 += rr[w][1]; l2 += rr[w][2]; l3 += rr[w][3]; }
            int best = 0; float bv = l0;
            if (l1 > bv) { bv = l1; best = 1; }
            if (l2 > bv) { bv = l2; best = 2; }
            if (l3 > bv) { bv = l3; best = 3; }
            s_top = best;
        }
        __syncthreads();
        if (c < CHAN) {
            float Q = ori[s_top][c];
            ysh[c] = fmaxf(LL - Q, 0.f) + fmaxf(HL - Q, 0.f)
                   + fmaxf(LH - Q, 0.f) + fmaxf(HHb - Q, 0.f);
        }
        __syncthreads();
        if (c < CHAN / 2) {
            const float* __restrict__ row = w1 + (size_t)c * CHAN;
            float acc = 0.f;
            #pragma unroll 8
            for (int k = 0; k < CHAN; k++) acc = fmaf(ysh[k], row[k], acc);
            hsh[c] = fmaxf(acc, 0.f);
        }
        __syncthreads();
        if (c < CHAN) {
            const float* __restrict__ row = w2 + (size_t)c * (CHAN / 2);
            float acc = 0.f;
            #pragma unroll 8
            for (int k = 0; k < CHAN / 2; k++) acc = fmaf(hsh[k], row[k], acc);
            g_scale[b * CHAN + c] = 1.0f / (1.0f + __expf(-acc));
            __threadfence();
        }
        __syncthreads();
        if (t == 0) atomicExch(&g_flag[b], old + 1u);   // = 256*(run+1)
    } else {
        // ---- wait for this run's head of batch b ----
        if (t == 0) {
            const unsigned target = (old & ~255u) + 256u;
            while (atomicAdd(&g_flag[b], 0u) < target) __nanosleep(64);
        }
        __syncthreads();
    }

    // ---------------- Phase 2: out = x * s (re-read own plane: L2 hit) ----
    const float s = __ldcg(&g_scale[plane]);
    float4* __restrict__ dst = (float4*)out + (size_t)plane * PLANE_V4;
    #pragma unroll 5
    for (int i = t; i < PLANE_V4; i += NT) {
        float4 v = p[i];
        v.x *= s; v.y *= s; v.z *= s; v.w *= s;
        __stcs(&dst[i], v);
    }
}

// ---------------------------------------------------------------------------
extern "C" void kernel_launch(void* const* d_in, const int* in_sizes, int n_in,
                              void* d_out, int out_size) {
    const float* x     = (const float*)d_in[0];  // [16,256,224,224]
    const float* w1    = (const float*)d_in[1];  // [128,256]
    const float* w2    = (const float*)d_in[2];  // [256,128]
    const float* w_enc = (const float*)d_in[3];  // [1,256]
    float* out = (float*)d_out;

    fused_kernel<<<NPLANES, NT>>>(x, out, w1, w2, w_enc);
}